// round 2
// baseline (speedup 1.0000x reference)
#include <cuda_runtime.h>
#include <math.h>

#define NN   1024     // nodes
#define EIN  4096     // raw edges
#define ET   5120     // edges + self loops
#define NTE  5119     // TE sample count (ET-1)
#define C1   16
#define C2   7
#define INC  1433
#define TE_BLOCK 256
#define TE_JT    1024                               // j-tile (float4) -> 16KB shared
#define NCHUNK  ((NTE + TE_BLOCK - 1) / TE_BLOCK)   // 20 i-chunks per channel

// ---------------- device scratch (no allocations allowed) ----------------
__device__ float  g_dig[NTE + 1];
__device__ float  g_h1[NN * C1];
__device__ float  g_h2[NN * C2];
__device__ float4 g_arr1[C1 * NTE];
__device__ float4 g_arr2[C2 * NTE];
__device__ float  g_tesum1[C1];
__device__ float  g_tesum2[C2];
__device__ float  g_agg1[NN * C1];
__device__ float  g_agg2[NN * C2];
__device__ float  g_cnt[NN];

__device__ __forceinline__ float f_inf() { return __int_as_float(0x7f800000); }

// ---------------- zero accumulators ----------------
__global__ void k_zero() {
    int t = blockIdx.x * blockDim.x + threadIdx.x;
    if (t < NN * C1) g_agg1[t] = 0.f;
    if (t < NN * C2) g_agg2[t] = 0.f;
    if (t < NN)      g_cnt[t]  = 0.f;
    if (t < C1)      g_tesum1[t] = 0.f;
    if (t < C2)      g_tesum2[t] = 0.f;
}

// ---------------- digamma table: g_dig[k] = psi(k), k = 1..NTE ----------------
__global__ void k_digamma() {
    int k = blockIdx.x * blockDim.x + threadIdx.x;
    if (k > NTE) return;
    if (k == 0) { g_dig[0] = 0.f; return; }     // never used (indices clamped >= 1)
    double x = (double)k, r = 0.0;
    while (x < 8.0) { r -= 1.0 / x; x += 1.0; }
    double ix = 1.0 / x, ix2 = ix * ix;
    r += log(x) - 0.5 * ix
       - ix2 * ((1.0/12.0) - ix2 * ((1.0/120.0) - ix2 * (1.0/252.0)));
    g_dig[k] = (float)r;
}

// ---------------- layer-1 GEMM: h1 = x @ W1^T + b1 (block/node, warp/channel) ----
__global__ void k_gemm1(const float* __restrict__ x,
                        const float* __restrict__ W1,
                        const float* __restrict__ b1) {
    int v    = blockIdx.x;
    int warp = threadIdx.x >> 5;     // 16 warps = 16 channels
    int lane = threadIdx.x & 31;
    const float* xr = x  + (size_t)v    * INC;
    const float* wr = W1 + (size_t)warp * INC;
    float s = 0.f;
    for (int k = lane; k < INC; k += 32) s += xr[k] * wr[k];
    #pragma unroll
    for (int o = 16; o; o >>= 1) s += __shfl_xor_sync(0xffffffffu, s, o);
    if (lane == 0) g_h1[v * C1 + warp] = s + b1[warp];
}

// ---------------- gather per-channel (x,y,z) embedded point arrays ----------------
__global__ void k_gather(const int* __restrict__ ei, int layer, int C) {
    int idx = blockIdx.x * blockDim.x + threadIdx.x;
    if (idx >= C * NTE) return;
    const float* h   = (layer == 1) ? g_h1   : g_h2;
    float4*      arr = (layer == 1) ? g_arr1 : g_arr2;
    int c = idx / NTE, i = idx - c * NTE;
    int s0 = (i  < EIN) ? ei[i]        : (i - EIN);
    int d0 = (i  < EIN) ? ei[EIN + i]  : (i - EIN);
    int i1 = i + 1;
    int s1 = (i1 < EIN) ? ei[i1]       : (i1 - EIN);
    arr[idx] = make_float4(h[d0 * C + c], h[s0 * C + c], h[s1 * C + c], 0.f);
}

// ---------------- KSG TE core: block = (channel, i-chunk) ----------------
__global__ __launch_bounds__(TE_BLOCK) void k_te(int layer) {
    const float4* __restrict__ arr = (layer == 1) ? g_arr1 : g_arr2;
    float* tesum = (layer == 1) ? g_tesum1 : g_tesum2;
    int c     = blockIdx.x / NCHUNK;
    int chunk = blockIdx.x - c * NCHUNK;
    int i     = chunk * TE_BLOCK + threadIdx.x;
    const float4* a = arr + c * NTE;

    __shared__ float4 tile[TE_JT];
    bool active = (i < NTE);
    float xi = 0.f, yi = 0.f, zi = 0.f;
    if (active) { float4 p = a[i]; xi = p.x; yi = p.y; zi = p.z; }

    // ---- pass 1: eps_i = min_{j != i} max(|dx|,|dy|,|dz|) ----
    float eps = f_inf();
    for (int j0 = 0; j0 < NTE; j0 += TE_JT) {
        int jn = min(TE_JT, NTE - j0);
        __syncthreads();
        for (int t = threadIdx.x; t < jn; t += TE_BLOCK) tile[t] = a[j0 + t];
        __syncthreads();
        int isel = i - j0;
        #pragma unroll 4
        for (int j = 0; j < jn; j++) {
            float4 q = tile[j];
            float m = fmaxf(fmaxf(fabsf(xi - q.x), fabsf(yi - q.y)), fabsf(zi - q.z));
            if (j != isel) eps = fminf(eps, m);
        }
    }

    // ---- pass 2: strict counts over ALL j (self cancels the -1/+1 in the ref) ----
    int cy = 0, cxy = 0, cyz = 0;
    for (int j0 = 0; j0 < NTE; j0 += TE_JT) {
        int jn = min(TE_JT, NTE - j0);
        __syncthreads();
        for (int t = threadIdx.x; t < jn; t += TE_BLOCK) tile[t] = a[j0 + t];
        __syncthreads();
        #pragma unroll 4
        for (int j = 0; j < jn; j++) {
            float4 q = tile[j];
            float dx = fabsf(xi - q.x);
            float dy = fabsf(yi - q.y);
            float dz = fabsf(zi - q.z);
            cy  += (dy < eps);
            cxy += (fmaxf(dx, dy) < eps);
            cyz += (fmaxf(dy, dz) < eps);
        }
    }
    cy  = max(cy,  1);   // eps>0 implies >=1 (self); clamp kills -inf NaN paths
    cxy = max(cxy, 1);
    cyz = max(cyz, 1);

    float val = active ? (g_dig[cy] - g_dig[cxy] - g_dig[cyz]) : 0.f;
    #pragma unroll
    for (int o = 16; o; o >>= 1) val += __shfl_xor_sync(0xffffffffu, val, o);
    __shared__ float red[TE_BLOCK / 32];
    int lane = threadIdx.x & 31, w = threadIdx.x >> 5;
    if (lane == 0) red[w] = val;
    __syncthreads();
    if (threadIdx.x == 0) {
        float s = 0.f;
        #pragma unroll
        for (int q = 0; q < TE_BLOCK / 32; q++) s += red[q];
        atomicAdd(&tesum[c], s);
    }
}

// ---------------- aggregation: agg[d,c] += sigmoid(tes_c * h[s,c]) ----------------
__global__ void k_agg(const int* __restrict__ ei, int layer, int C) {
    int idx = blockIdx.x * blockDim.x + threadIdx.x;
    if (idx >= ET * C) return;
    const float* h     = (layer == 1) ? g_h1 : g_h2;
    const float* tesum = (layer == 1) ? g_tesum1 : g_tesum2;
    float*       agg   = (layer == 1) ? g_agg1 : g_agg2;
    int e = idx / C, c = idx - e * C;
    int s = (e < EIN) ? ei[e]       : (e - EIN);
    int d = (e < EIN) ? ei[EIN + e] : (e - EIN);
    float tes = -0.57721566490153286f + tesum[c] * (1.0f / (float)NTE);
    if (layer == 2) tes *= 0.5f;
    float m = 1.0f / (1.0f + expf(-tes * h[s * C + c]));
    atomicAdd(&agg[d * C + c], m);
    if (layer == 1 && c == 0) atomicAdd(&g_cnt[d], 1.0f);
}

// ---------------- layer-2 GEMM: h2 = relu(agg1/cnt) @ W2^T + b2 ----------------
__global__ void k_gemm2(const float* __restrict__ W2, const float* __restrict__ b2) {
    int v = blockIdx.x * blockDim.x + threadIdx.x;
    if (v >= NN) return;
    float inv = 1.0f / fmaxf(g_cnt[v], 1.0f);
    float hv[C1];
    #pragma unroll
    for (int cc = 0; cc < C1; cc++) hv[cc] = fmaxf(g_agg1[v * C1 + cc] * inv, 0.0f);
    #pragma unroll
    for (int o = 0; o < C2; o++) {
        float s = b2[o];
        #pragma unroll
        for (int cc = 0; cc < C1; cc++) s += W2[o * C1 + cc] * hv[cc];
        g_h2[v * C2 + o] = s;
    }
}

// ---------------- final: mean + log_softmax ----------------
__global__ void k_final(float* __restrict__ out) {
    int v = blockIdx.x * blockDim.x + threadIdx.x;
    if (v >= NN) return;
    float inv = 1.0f / fmaxf(g_cnt[v], 1.0f);
    float val[C2], mx = -f_inf();
    #pragma unroll
    for (int o = 0; o < C2; o++) {
        val[o] = g_agg2[v * C2 + o] * inv;
        mx = fmaxf(mx, val[o]);
    }
    float s = 0.f;
    #pragma unroll
    for (int o = 0; o < C2; o++) s += expf(val[o] - mx);
    float ls = mx + logf(s);
    #pragma unroll
    for (int o = 0; o < C2; o++) out[v * C2 + o] = val[o] - ls;
}

// ---------------- launch: identify inputs by element count (order-proof) ----------
extern "C" void kernel_launch(void* const* d_in, const int* in_sizes, int n_in,
                              void* d_out, int out_size) {
    const float* x  = nullptr;
    const int*   ei = nullptr;
    const float* W1 = nullptr;
    const float* b1 = nullptr;
    const float* W2 = nullptr;
    const float* b2 = nullptr;
    for (int k = 0; k < n_in; k++) {
        switch (in_sizes[k]) {
            case NN * INC:  x  = (const float*)d_in[k]; break;   // 1467392
            case 2 * EIN:   ei = (const int*)  d_in[k]; break;   // 8192
            case C1 * INC:  W1 = (const float*)d_in[k]; break;   // 22928
            case C1:        b1 = (const float*)d_in[k]; break;   // 16
            case C2 * C1:   W2 = (const float*)d_in[k]; break;   // 112
            case C2:        b2 = (const float*)d_in[k]; break;   // 7
            default: break;
        }
    }
    float* out = (float*)d_out;

    k_zero   <<<(NN * C1 + 255) / 256, 256>>>();
    k_digamma<<<(NTE + 1 + 255) / 256, 256>>>();

    // layer 1
    k_gemm1  <<<NN, 512>>>(x, W1, b1);
    k_gather <<<(C1 * NTE + 255) / 256, 256>>>(ei, 1, C1);
    k_te     <<<C1 * NCHUNK, TE_BLOCK>>>(1);
    k_agg    <<<(ET * C1 + 255) / 256, 256>>>(ei, 1, C1);

    // layer 2
    k_gemm2  <<<(NN + 255) / 256, 256>>>(W2, b2);
    k_gather <<<(C2 * NTE + 255) / 256, 256>>>(ei, 2, C2);
    k_te     <<<C2 * NCHUNK, TE_BLOCK>>>(2);
    k_agg    <<<(ET * C2 + 255) / 256, 256>>>(ei, 2, C2);

    k_final  <<<(NN + 255) / 256, 256>>>(out);
}